// round 16
// baseline (speedup 1.0000x reference)
#include <cuda_runtime.h>
#include <cuda_bf16.h>
#include <math_constants.h>

// Problem constants
#define BATCH   2
#define NPTS    8192
#define KNN     11        // k+1 including self
#define LEN_IN  66        // 3*11 + 3*10 + 3
#define TPB     128
#define NGROUP  4         // split-K over candidates
#define QPB     (TPB / NGROUP)        // 32 queries per block
#define GRANGE  (NPTS / NGROUP)       // 2048 candidates per group
#define GPAIR   (GRANGE / 2)          // 1024 pairs per group
#define PAIRS_PER_BATCH (NPTS / 2)    // 4096
#define BUCK_CAP    24                // per-thread staging slots
#define BUCK_FLUSH  8                 // flush when any lane reaches this

typedef unsigned long long ull;

// Device scratch (static; no allocations allowed)
__device__ float g_W12[LEN_IN * 16];
__device__ float g_Wc [LEN_IN * 6];
__device__ float g_bc [6];
// Pair-packed candidate arrays: [batch][pair] -> ((x0,x1),(y0,y1)) / ((z0,z1),(sq0,sq1))
__device__ ulonglong2 g_xy[BATCH * PAIRS_PER_BATCH];   // 128KB
__device__ ulonglong2 g_zw[BATCH * PAIRS_PER_BATCH];   // 128KB

// ---- packed f32x2 helpers (each lane is bit-identical to the scalar op) ----
__device__ __forceinline__ ull mul2(ull a, ull b) {
    ull r; asm("mul.rn.f32x2 %0, %1, %2;" : "=l"(r) : "l"(a), "l"(b)); return r;
}
__device__ __forceinline__ ull add2(ull a, ull b) {
    ull r; asm("add.rn.f32x2 %0, %1, %2;" : "=l"(r) : "l"(a), "l"(b)); return r;
}
__device__ __forceinline__ ull fma2(ull a, ull b, ull c) {
    ull r; asm("fma.rn.f32x2 %0, %1, %2, %3;" : "=l"(r) : "l"(a), "l"(b), "l"(c)); return r;
}
__device__ __forceinline__ ull pack2(float lo, float hi) {
    return (ull)__float_as_uint(lo) | ((ull)__float_as_uint(hi) << 32);
}
__device__ __forceinline__ void unpack2(ull v, float& lo, float& hi) {
    asm("mov.b64 {%0, %1}, %2;" : "=f"(lo), "=f"(hi) : "l"(v));
}

// ---------------------------------------------------------------------------
// Prologue 1: collapse W1@W2@W3 and the bias chain (tiny, one block).
// The reference MLP has no activation functions, so the whole head is affine.
// ---------------------------------------------------------------------------
__global__ void combine_weights_kernel(const float* __restrict__ W1,
                                       const float* __restrict__ b1,
                                       const float* __restrict__ W2,
                                       const float* __restrict__ b2,
                                       const float* __restrict__ W3,
                                       const float* __restrict__ b3)
{
    int t = threadIdx.x;
    for (int e = t; e < LEN_IN * 16; e += blockDim.x) {
        int r = e / 16, c = e % 16;
        float s = 0.f;
        for (int k = 0; k < 32; ++k) s += W1[r * 32 + k] * W2[k * 16 + c];
        g_W12[e] = s;
    }
    __syncthreads();
    for (int e = t; e < LEN_IN * 6; e += blockDim.x) {
        int r = e / 6, c = e % 6;
        float s = 0.f;
        for (int k = 0; k < 16; ++k) s += g_W12[r * 16 + k] * W3[k * 6 + c];
        g_Wc[e] = s;
    }
    if (t < 6) {
        float s = b3[t];
        for (int k = 0; k < 16; ++k) {
            float tb = b2[k];
            for (int m = 0; m < 32; ++m) tb += b1[m] * W2[m * 16 + k];
            s += tb * W3[k * 6 + t];
        }
        g_bc[t] = s;
    }
}

// ---------------------------------------------------------------------------
// Prologue 2: pack candidates into pair-packed SoA once (sq with the EXACT
// fmaf recipe used everywhere, so self-distance stays exactly 0).
// ---------------------------------------------------------------------------
__global__ void pack_pairs_kernel(const float* __restrict__ pos)
{
    const int t = blockIdx.x * blockDim.x + threadIdx.x;
    if (t >= BATCH * PAIRS_PER_BATCH) return;
    const int b  = t / PAIRS_PER_BATCH;
    const int pr = t - b * PAIRS_PER_BATCH;
    const float* bp = pos + (size_t)b * NPTS * 3 + (size_t)pr * 6;
    const float x0 = bp[0], y0 = bp[1], z0 = bp[2];
    const float x1 = bp[3], y1 = bp[4], z1 = bp[5];
    float s0 = x0 * x0; s0 = fmaf(y0, y0, s0); s0 = fmaf(z0, z0, s0);
    float s1 = x1 * x1; s1 = fmaf(y1, y1, s1); s1 = fmaf(z1, z1, s1);
    g_xy[t] = make_ulonglong2(pack2(x0, x1), pack2(y0, y1));
    g_zw[t] = make_ulonglong2(pack2(z0, z1), pack2(s0, s1));
}

// ---------------------------------------------------------------------------
// Main fused kernel: split-K brute-force kNN (top-11 by d2), candidates
// streamed straight from L2 (no smem tile, NO mid-kernel barriers), packed
// f32x2 distance math, pair-level guard, slot-major staged buckets, exact
// serial strict-'<' chain + 4-way merge + collapsed linear head.
//   Block = 32 queries x 4 candidate groups (128 threads, 1 group per warp).
// ---------------------------------------------------------------------------
__global__ void __launch_bounds__(TPB)
knn_mlp_kernel(const float* __restrict__ pos,
               const float* __restrict__ vel,
               const float* __restrict__ initc,
               float* __restrict__ out)
{
    __shared__ float  s_bdk[BUCK_CAP * TPB];       // staged d2, slot-major (12KB)
    __shared__ int    s_bik[BUCK_CAP * TPB];       // staged idx, slot-major (12KB)
    __shared__ float  s_md[TPB * KNN];             // partial top-11 distances
    __shared__ int    s_mi[TPB * KNN];             // partial top-11 indices
    __shared__ float  s_Wc[LEN_IN * 6];
    __shared__ float  s_bc[6];

    const int tid  = threadIdx.x;
    const int grp  = tid >> 5;                     // 0..3  (== warp id)
    const int qloc = tid & (QPB - 1);              // query within block
    const int q    = blockIdx.x * QPB + qloc;      // global query id
    const int bb   = q >> 13;                      // q / 8192 (batch)
    const int i    = q & (NPTS - 1);

    const float* __restrict__ bpos = pos + (size_t)bb * NPTS * 3;
    const float* __restrict__ bvel = vel + (size_t)bb * NPTS * 3;

    for (int t = tid; t < LEN_IN * 6; t += TPB) s_Wc[t] = g_Wc[t];
    if (tid < 6) s_bc[tid] = g_bc[tid];

    // Query point; sq computed with the SAME op sequence as pack_pairs so
    // the self-distance is exactly 0 (round-5 passing recipe, unchanged).
    const float qx = bpos[i * 3 + 0];
    const float qy = bpos[i * 3 + 1];
    const float qz = bpos[i * 3 + 2];
    float qs = qx * qx; qs = fmaf(qy, qy, qs); qs = fmaf(qz, qz, qs);

    // Packed query constants
    const ull qxx = pack2(qx, qx);
    const ull qyy = pack2(qy, qy);
    const ull qzz = pack2(qz, qz);
    const ull qss = pack2(qs, qs);
    const ull m22 = pack2(-2.0f, -2.0f);

    // Per-group sorted top-11 (ascending), register-resident.
    float bd[KNN];
    int   bi[KNN];
#pragma unroll
    for (int k = 0; k < KNN; ++k) { bd[k] = CUDART_INF_F; bi[k] = 0; }

    int   cnt = 0;
    float tau = CUDART_INF_F;

    // This warp's candidate pair stream (uniform address across lanes ->
    // warp-broadcast LDG, one 16B line per load).
    const ulonglong2* __restrict__ myXY = g_xy + bb * PAIRS_PER_BATCH + grp * GPAIR;
    const ulonglong2* __restrict__ myZW = g_zw + bb * PAIRS_PER_BATCH + grp * GPAIR;
    const int idxbase = grp * GRANGE;

    for (int ptb = 0; ptb < GPAIR; ptb += 8) {
#pragma unroll
        for (int v = 0; v < 8; ++v) {
            const int pt = ptb + v;
            const ulonglong2 xy = __ldg(myXY + pt);
            const ulonglong2 zw = __ldg(myZW + pt);
            // Packed distance: lanes identical to the scalar recipe
            // d = qx*x; d = fma(qy,y,d); d = fma(qz,z,d);
            // d2 = fma(-2, d, qs + sq)
            ull dd = mul2(qxx, xy.x);
            dd = fma2(qyy, xy.y, dd);
            dd = fma2(qzz, zw.x, dd);
            const ull tt = add2(qss, zw.y);
            const ull rr = fma2(m22, dd, tt);
            float d2lo, d2hi;
            unpack2(rr, d2lo, d2hi);
            // Pair-level guard; staging order lo-then-hi == scan order.
            if (fminf(d2lo, d2hi) < tau) {
                if (d2lo < tau) {
                    s_bdk[cnt * TPB + tid] = d2lo;
                    s_bik[cnt * TPB + tid] = idxbase + 2 * pt;
                    ++cnt;
                }
                if (d2hi < tau) {
                    s_bdk[cnt * TPB + tid] = d2hi;
                    s_bik[cnt * TPB + tid] = idxbase + 2 * pt + 1;
                    ++cnt;
                }
            }
        }
        // Warp-coherent flush when any lane's bucket reaches threshold.
        // (<=16 appends between checks; 7 + 16 = 23 <= BUCK_CAP=24.)
        if (__ballot_sync(0xFFFFFFFFu, cnt >= BUCK_FLUSH)) {
            // Replay staged items in scan order through the EXACT serial
            // strict-'<' chain (round-5/9/11 passing semantics, which is
            // bug-compatible with the reference TopK on duplicate d2).
            // Replaying a superset of qualifying candidates is a no-op for
            // the non-qualifying ones, so stale-tau staging is bit-exact.
            for (int u = 0; u < cnt; ++u) {
                float dv = s_bdk[u * TPB + tid];
                if (dv < bd[KNN - 1]) {
                    int id = s_bik[u * TPB + tid];
#pragma unroll
                    for (int k = 0; k < KNN; ++k) {
                        if (dv < bd[k]) {
                            float td = bd[k]; bd[k] = dv; dv = td;
                            int   ti = bi[k]; bi[k] = id; id = ti;
                        }
                    }
                }
            }
            cnt = 0;
            tau = bd[KNN - 1];
        }
    }
    // Flush remaining staged candidates.
    for (int u = 0; u < cnt; ++u) {
        float dv = s_bdk[u * TPB + tid];
        if (dv < bd[KNN - 1]) {
            int id = s_bik[u * TPB + tid];
#pragma unroll
            for (int k = 0; k < KNN; ++k) {
                if (dv < bd[k]) {
                    float td = bd[k]; bd[k] = dv; dv = td;
                    int   ti = bi[k]; bi[k] = id; id = ti;
                }
            }
        }
    }

    // Publish partial lists.
#pragma unroll
    for (int k = 0; k < KNN; ++k) {
        s_md[tid * KNN + k] = bd[k];
        s_mi[tid * KNN + k] = bi[k];
    }
    __syncthreads();

    // Threads 0..31 merge their query's four sorted lists sequentially.
    // On equal d2 the lower group wins (its indices are all lower) —
    // same tie rule as the passing round-9/11/14/15 merges.
    if (tid < QPB) {
        float m1d[KNN]; int m1i[KNN];
        {
            const int a = (0 * QPB + tid) * KNN;
            const int b = (1 * QPB + tid) * KNN;
            int ia = 0, ib = 0;
#pragma unroll
            for (int k = 0; k < KNN; ++k) {
                const float da = s_md[a + ia];
                const float db = s_md[b + ib];
                if (da <= db) { m1d[k] = da; m1i[k] = s_mi[a + ia]; ++ia; }
                else          { m1d[k] = db; m1i[k] = s_mi[b + ib]; ++ib; }
            }
        }
        float m2d[KNN]; int m2i[KNN];
        {
            const int b = (2 * QPB + tid) * KNN;
            int ia = 0, ib = 0;
#pragma unroll
            for (int k = 0; k < KNN; ++k) {
                const float da = m1d[ia];
                const float db = s_md[b + ib];
                if (da <= db) { m2d[k] = da; m2i[k] = m1i[ia]; ++ia; }
                else          { m2d[k] = db; m2i[k] = s_mi[b + ib]; ++ib; }
            }
        }
        int fi[KNN];
        {
            const int b = (3 * QPB + tid) * KNN;
            int ia = 0, ib = 0;
#pragma unroll
            for (int k = 0; k < KNN; ++k) {
                const float da = m2d[ia];
                const float db = s_md[b + ib];
                if (da <= db) { fi[k] = m2i[ia]; ++ia; }
                else          { fi[k] = s_mi[b + ib]; ++ib; }
            }
        }

        // ---- gather features and apply collapsed linear head ----
        const int qq  = blockIdx.x * QPB + tid;
        const int bb2 = qq >> 13;
        const int ii  = qq & (NPTS - 1);
        const float* __restrict__ bpos2 = pos + (size_t)bb2 * NPTS * 3;
        const float* __restrict__ bvel2 = vel + (size_t)bb2 * NPTS * 3;
        const float qx2 = bpos2[ii * 3 + 0];
        const float qy2 = bpos2[ii * 3 + 1];
        const float qz2 = bpos2[ii * 3 + 2];

        float acc[6];
#pragma unroll
        for (int c = 0; c < 6; ++c) acc[c] = s_bc[c];

#pragma unroll
        for (int r = 0; r < KNN; ++r) {
            const int j = fi[r];
            const float vx = bvel2[j * 3 + 0];
            const float vy = bvel2[j * 3 + 1];
            const float vz = bvel2[j * 3 + 2];
            const int row = 3 * r;
#pragma unroll
            for (int c = 0; c < 6; ++c) {
                acc[c] = fmaf(vx, s_Wc[(row + 0) * 6 + c], acc[c]);
                acc[c] = fmaf(vy, s_Wc[(row + 1) * 6 + c], acc[c]);
                acc[c] = fmaf(vz, s_Wc[(row + 2) * 6 + c], acc[c]);
            }
        }
#pragma unroll
        for (int r = 1; r < KNN; ++r) {
            const int j = fi[r];
            const float ox = bpos2[j * 3 + 0] - qx2;
            const float oy = bpos2[j * 3 + 1] - qy2;
            const float oz = bpos2[j * 3 + 2] - qz2;
            const int row = 33 + 3 * (r - 1);
#pragma unroll
            for (int c = 0; c < 6; ++c) {
                acc[c] = fmaf(ox, s_Wc[(row + 0) * 6 + c], acc[c]);
                acc[c] = fmaf(oy, s_Wc[(row + 1) * 6 + c], acc[c]);
                acc[c] = fmaf(oz, s_Wc[(row + 2) * 6 + c], acc[c]);
            }
        }
        {
            const float i0 = initc[bb2 * 3 + 0];
            const float i1 = initc[bb2 * 3 + 1];
            const float i2 = initc[bb2 * 3 + 2];
#pragma unroll
            for (int c = 0; c < 6; ++c) {
                acc[c] = fmaf(i0, s_Wc[63 * 6 + c], acc[c]);
                acc[c] = fmaf(i1, s_Wc[64 * 6 + c], acc[c]);
                acc[c] = fmaf(i2, s_Wc[65 * 6 + c], acc[c]);
            }
        }

        float* o = out + (size_t)qq * 6;
        o[0] = acc[0] + qx2;
        o[1] = acc[1] + qy2;
        o[2] = acc[2] + qz2;
        o[3] = acc[3];
        o[4] = acc[4];
        o[5] = acc[5];
    }
}

// ---------------------------------------------------------------------------
extern "C" void kernel_launch(void* const* d_in, const int* in_sizes, int n_in,
                              void* d_out, int out_size)
{
    const float* position = (const float*)d_in[0];
    const float* velocity = (const float*)d_in[1];
    const float* initcfg  = (const float*)d_in[2];
    const float* W1 = (const float*)d_in[3];
    const float* b1 = (const float*)d_in[4];
    const float* W2 = (const float*)d_in[5];
    const float* b2 = (const float*)d_in[6];
    const float* W3 = (const float*)d_in[7];
    const float* b3 = (const float*)d_in[8];
    float* out = (float*)d_out;

    combine_weights_kernel<<<1, 256>>>(W1, b1, W2, b2, W3, b3);
    pack_pairs_kernel<<<(BATCH * PAIRS_PER_BATCH + 255) / 256, 256>>>(position);

    const int total = BATCH * NPTS;           // 16384 queries
    knn_mlp_kernel<<<total / QPB, TPB>>>(position, velocity, initcfg, out);
}

// round 17
// speedup vs baseline: 1.5258x; 1.5258x over previous
#include <cuda_runtime.h>
#include <cuda_bf16.h>
#include <math_constants.h>

// Problem constants
#define BATCH   2
#define NPTS    8192
#define KNN     11        // k+1 including self
#define LEN_IN  66        // 3*11 + 3*10 + 3
#define TPB     128
#define NGROUP  4         // split-K over candidates
#define QPB     (TPB / NGROUP)        // 32 queries per block
#define GRANGE  (NPTS / NGROUP)       // 2048 candidates per group
#define GPAIR   (GRANGE / 2)          // 1024 pairs per group
#define PPB     (NPTS / 2)            // 4096 pairs per batch
#define CPAIR   128                   // pairs per group per chunk
#define NPGC    (NGROUP * CPAIR)      // 512 tile entries per buffer
#define NITER   (GPAIR / CPAIR)       // 8
#define BUCK_CAP    16                // per-thread staging slots
#define BUCK_FLUSH  8                 // flush when any lane reaches this

typedef unsigned long long ull;

// Device scratch (static; no allocations allowed)
__device__ float g_W12[LEN_IN * 16];
__device__ float g_Wc [LEN_IN * 6];
__device__ float g_bc [6];
// Pair-packed candidate arrays: [batch][pair] -> ((x0,x1),(y0,y1)) / ((z0,z1),(sq0,sq1))
__device__ ulonglong2 g_xy[BATCH * PPB];   // 128KB
__device__ ulonglong2 g_zw[BATCH * PPB];   // 128KB

// ---- packed f32x2 helpers (each lane is bit-identical to the scalar op) ----
__device__ __forceinline__ ull mul2(ull a, ull b) {
    ull r; asm("mul.rn.f32x2 %0, %1, %2;" : "=l"(r) : "l"(a), "l"(b)); return r;
}
__device__ __forceinline__ ull add2(ull a, ull b) {
    ull r; asm("add.rn.f32x2 %0, %1, %2;" : "=l"(r) : "l"(a), "l"(b)); return r;
}
__device__ __forceinline__ ull fma2(ull a, ull b, ull c) {
    ull r; asm("fma.rn.f32x2 %0, %1, %2, %3;" : "=l"(r) : "l"(a), "l"(b), "l"(c)); return r;
}
__device__ __forceinline__ ull pack2(float lo, float hi) {
    return (ull)__float_as_uint(lo) | ((ull)__float_as_uint(hi) << 32);
}
__device__ __forceinline__ void unpack2(ull v, float& lo, float& hi) {
    asm("mov.b64 {%0, %1}, %2;" : "=f"(lo), "=f"(hi) : "l"(v));
}
__device__ __forceinline__ void cpasync16(void* smem_ptr, const void* gptr) {
    unsigned sa = (unsigned)__cvta_generic_to_shared(smem_ptr);
    asm volatile("cp.async.cg.shared.global [%0], [%1], 16;" :: "r"(sa), "l"(gptr));
}
#define CP_COMMIT() asm volatile("cp.async.commit_group;" ::: "memory")
#define CP_WAIT0()  asm volatile("cp.async.wait_group 0;"  ::: "memory")

// ---------------------------------------------------------------------------
// Prologue (single launch): block 0 collapses W1@W2@W3 + bias chain; blocks
// 1..32 pack candidates into pair-packed SoA (sq with the EXACT fmaf recipe
// used by the main kernel, so self-distance stays exactly 0).
// ---------------------------------------------------------------------------
__global__ void prologue_kernel(const float* __restrict__ pos,
                                const float* __restrict__ W1,
                                const float* __restrict__ b1,
                                const float* __restrict__ W2,
                                const float* __restrict__ b2,
                                const float* __restrict__ W3,
                                const float* __restrict__ b3)
{
    const int t = threadIdx.x;
    if (blockIdx.x == 0) {
        __shared__ float s_t1[16];
        for (int e = t; e < LEN_IN * 16; e += blockDim.x) {
            int r = e / 16, c = e % 16;
            float s = 0.f;
            for (int k = 0; k < 32; ++k) s += W1[r * 32 + k] * W2[k * 16 + c];
            g_W12[e] = s;
        }
        if (t < 16) {
            float s = b2[t];
            for (int m = 0; m < 32; ++m) s += b1[m] * W2[m * 16 + t];
            s_t1[t] = s;
        }
        __syncthreads();
        for (int e = t; e < LEN_IN * 6; e += blockDim.x) {
            int r = e / 6, c = e % 6;
            float s = 0.f;
            for (int k = 0; k < 16; ++k) s += g_W12[r * 16 + k] * W3[k * 6 + c];
            g_Wc[e] = s;
        }
        if (t < 6) {
            float s = b3[t];
            for (int k = 0; k < 16; ++k) s += s_t1[k] * W3[k * 6 + t];
            g_bc[t] = s;
        }
    } else {
        const int p = (blockIdx.x - 1) * blockDim.x + t;   // pair id, 0..8191
        if (p < BATCH * PPB) {
            const int b  = p / PPB;
            const int pr = p - b * PPB;
            const float* bp = pos + (size_t)b * NPTS * 3 + (size_t)pr * 6;
            const float x0 = bp[0], y0 = bp[1], z0 = bp[2];
            const float x1 = bp[3], y1 = bp[4], z1 = bp[5];
            float s0 = x0 * x0; s0 = fmaf(y0, y0, s0); s0 = fmaf(z0, z0, s0);
            float s1 = x1 * x1; s1 = fmaf(y1, y1, s1); s1 = fmaf(z1, z1, s1);
            g_xy[p] = make_ulonglong2(pack2(x0, x1), pack2(y0, y1));
            g_zw[p] = make_ulonglong2(pack2(z0, z1), pack2(s0, s1));
        }
    }
}

// ---------------------------------------------------------------------------
// Main fused kernel: split-K brute-force kNN (top-11 by d2) with cp.async
// double-buffered tiles (ONE barrier per chunk, loads overlapped with scan),
// packed f32x2 distance math, pair-level guard, slot-major staged buckets,
// exact serial strict-'<' chain + 4-way merge + collapsed linear head.
//   Block = 32 queries x 4 candidate groups (128 threads, 1 group per warp).
// ---------------------------------------------------------------------------
__global__ void __launch_bounds__(TPB, 4)
knn_mlp_kernel(const float* __restrict__ pos,
               const float* __restrict__ vel,
               const float* __restrict__ initc,
               float* __restrict__ out)
{
    __shared__ ulonglong2 sXY[2][NPGC];            // 16KB (double-buffered)
    __shared__ ulonglong2 sZW[2][NPGC];            // 16KB
    __shared__ float  s_bdk[BUCK_CAP * TPB];       // staged d2, slot-major (8KB)
    __shared__ int    s_bik[BUCK_CAP * TPB];       // staged idx, slot-major (8KB)
    __shared__ float  s_Wc[LEN_IN * 6];
    __shared__ float  s_bc[6];

    // After the scan, tile buffer 0 is dead: alias the merge lists onto it.
    float* const s_md = reinterpret_cast<float*>(&sXY[0][0]);  // TPB*KNN = 5.6KB <= 8KB
    int*   const s_mi = reinterpret_cast<int*>(&sZW[0][0]);    // TPB*KNN = 5.6KB <= 8KB

    const int tid  = threadIdx.x;
    const int grp  = tid >> 5;                     // 0..3  (== warp id)
    const int qloc = tid & (QPB - 1);              // query within block
    const int q    = blockIdx.x * QPB + qloc;      // global query id
    const int bb   = q >> 13;                      // q / 8192 (batch)
    const int i    = q & (NPTS - 1);

    const float* __restrict__ bpos = pos + (size_t)bb * NPTS * 3;
    const float* __restrict__ bvel = vel + (size_t)bb * NPTS * 3;

    for (int t = tid; t < LEN_IN * 6; t += TPB) s_Wc[t] = g_Wc[t];
    if (tid < 6) s_bc[tid] = g_bc[tid];

    // Query point; sq computed with the SAME op sequence as the packer so
    // the self-distance is exactly 0 (round-5 passing recipe, unchanged).
    const float qx = bpos[i * 3 + 0];
    const float qy = bpos[i * 3 + 1];
    const float qz = bpos[i * 3 + 2];
    float qs = qx * qx; qs = fmaf(qy, qy, qs); qs = fmaf(qz, qz, qs);

    // Packed query constants
    const ull qxx = pack2(qx, qx);
    const ull qyy = pack2(qy, qy);
    const ull qzz = pack2(qz, qz);
    const ull qss = pack2(qs, qs);
    const ull m22 = pack2(-2.0f, -2.0f);

    // Per-group sorted top-11 (ascending), register-resident.
    float bd[KNN];
    int   bi[KNN];
#pragma unroll
    for (int k = 0; k < KNN; ++k) { bd[k] = CUDART_INF_F; bi[k] = 0; }

    int   cnt = 0;
    float tau = CUDART_INF_F;

    const ulonglong2* __restrict__ gXY = g_xy + bb * PPB;
    const ulonglong2* __restrict__ gZW = g_zw + bb * PPB;

    // ---- async tile loader: raw 16B copies of the pre-packed arrays ----
    auto load_tile = [&](int it, int buf) {
#pragma unroll
        for (int t = tid; t < NPGC; t += TPB) {
            const int g = t >> 7;                  // t / CPAIR
            const int r = t & (CPAIR - 1);
            const int src = g * GPAIR + it * CPAIR + r;
            cpasync16(&sXY[buf][t], gXY + src);
            cpasync16(&sZW[buf][t], gZW + src);
        }
    };

    load_tile(0, 0);
    CP_COMMIT();

    for (int it = 0; it < NITER; ++it) {
        const int buf = it & 1;
        CP_WAIT0();          // data for chunk `it` landed (own thread's copies)
        __syncthreads();     // cross-thread visibility + all warps done scanning buf^1
        if (it + 1 < NITER) { load_tile(it + 1, buf ^ 1); CP_COMMIT(); }

        const ulonglong2* __restrict__ myXY = &sXY[buf][grp * CPAIR];
        const ulonglong2* __restrict__ myZW = &sZW[buf][grp * CPAIR];
        const int idxbase = grp * GRANGE + it * (2 * CPAIR);

        for (int ptb = 0; ptb < CPAIR; ptb += 4) {
#pragma unroll
            for (int v = 0; v < 4; ++v) {
                const int pt = ptb + v;
                const ulonglong2 xy = myXY[pt];
                const ulonglong2 zw = myZW[pt];
                // Packed distance: lanes identical to the scalar recipe
                // d = qx*x; d = fma(qy,y,d); d = fma(qz,z,d);
                // d2 = fma(-2, d, qs + sq)
                ull dd = mul2(qxx, xy.x);
                dd = fma2(qyy, xy.y, dd);
                dd = fma2(qzz, zw.x, dd);
                const ull tt = add2(qss, zw.y);
                const ull rr = fma2(m22, dd, tt);
                float d2lo, d2hi;
                unpack2(rr, d2lo, d2hi);
                // Pair-level guard; staging order lo-then-hi == scan order.
                if (fminf(d2lo, d2hi) < tau) {
                    if (d2lo < tau) {
                        s_bdk[cnt * TPB + tid] = d2lo;
                        s_bik[cnt * TPB + tid] = idxbase + 2 * pt;
                        ++cnt;
                    }
                    if (d2hi < tau) {
                        s_bdk[cnt * TPB + tid] = d2hi;
                        s_bik[cnt * TPB + tid] = idxbase + 2 * pt + 1;
                        ++cnt;
                    }
                }
            }
            // Warp-coherent flush when any lane's bucket reaches threshold.
            // (<=8 appends between checks; 7 + 8 = 15 <= BUCK_CAP=16.)
            if (__ballot_sync(0xFFFFFFFFu, cnt >= BUCK_FLUSH)) {
                // Replay staged items in scan order through the EXACT serial
                // strict-'<' chain (round-5/9/11 passing semantics). Replaying
                // a superset of qualifying candidates is a no-op for the
                // non-qualifying ones, so stale-tau staging is bit-exact.
                for (int u = 0; u < cnt; ++u) {
                    float dv = s_bdk[u * TPB + tid];
                    if (dv < bd[KNN - 1]) {
                        int id = s_bik[u * TPB + tid];
#pragma unroll
                        for (int k = 0; k < KNN; ++k) {
                            if (dv < bd[k]) {
                                float td = bd[k]; bd[k] = dv; dv = td;
                                int   ti = bi[k]; bi[k] = id; id = ti;
                            }
                        }
                    }
                }
                cnt = 0;
                tau = bd[KNN - 1];
            }
        }
    }
    // Flush remaining staged candidates.
    for (int u = 0; u < cnt; ++u) {
        float dv = s_bdk[u * TPB + tid];
        if (dv < bd[KNN - 1]) {
            int id = s_bik[u * TPB + tid];
#pragma unroll
            for (int k = 0; k < KNN; ++k) {
                if (dv < bd[k]) {
                    float td = bd[k]; bd[k] = dv; dv = td;
                    int   ti = bi[k]; bi[k] = id; id = ti;
                }
            }
        }
    }

    // All warps done scanning before we overwrite tile buffer 0 (aliased).
    __syncthreads();

    // Publish partial lists.
#pragma unroll
    for (int k = 0; k < KNN; ++k) {
        s_md[tid * KNN + k] = bd[k];
        s_mi[tid * KNN + k] = bi[k];
    }
    __syncthreads();

    // Threads 0..31 merge their query's four sorted lists sequentially.
    // On equal d2 the lower group wins (its indices are all lower) —
    // same tie rule as the passing round-9/11/14/15 merges.
    if (tid < QPB) {
        float m1d[KNN]; int m1i[KNN];
        {
            const int a = (0 * QPB + tid) * KNN;
            const int b = (1 * QPB + tid) * KNN;
            int ia = 0, ib = 0;
#pragma unroll
            for (int k = 0; k < KNN; ++k) {
                const float da = s_md[a + ia];
                const float db = s_md[b + ib];
                if (da <= db) { m1d[k] = da; m1i[k] = s_mi[a + ia]; ++ia; }
                else          { m1d[k] = db; m1i[k] = s_mi[b + ib]; ++ib; }
            }
        }
        float m2d[KNN]; int m2i[KNN];
        {
            const int b = (2 * QPB + tid) * KNN;
            int ia = 0, ib = 0;
#pragma unroll
            for (int k = 0; k < KNN; ++k) {
                const float da = m1d[ia];
                const float db = s_md[b + ib];
                if (da <= db) { m2d[k] = da; m2i[k] = m1i[ia]; ++ia; }
                else          { m2d[k] = db; m2i[k] = s_mi[b + ib]; ++ib; }
            }
        }
        int fi[KNN];
        {
            const int b = (3 * QPB + tid) * KNN;
            int ia = 0, ib = 0;
#pragma unroll
            for (int k = 0; k < KNN; ++k) {
                const float da = m2d[ia];
                const float db = s_md[b + ib];
                if (da <= db) { fi[k] = m2i[ia]; ++ia; }
                else          { fi[k] = s_mi[b + ib]; ++ib; }
            }
        }

        // ---- gather features and apply collapsed linear head ----
        const int qq  = blockIdx.x * QPB + tid;
        const int bb2 = qq >> 13;
        const int ii  = qq & (NPTS - 1);
        const float* __restrict__ bpos2 = pos + (size_t)bb2 * NPTS * 3;
        const float* __restrict__ bvel2 = vel + (size_t)bb2 * NPTS * 3;
        const float qx2 = bpos2[ii * 3 + 0];
        const float qy2 = bpos2[ii * 3 + 1];
        const float qz2 = bpos2[ii * 3 + 2];

        float acc[6];
#pragma unroll
        for (int c = 0; c < 6; ++c) acc[c] = s_bc[c];

#pragma unroll
        for (int r = 0; r < KNN; ++r) {
            const int j = fi[r];
            const float vx = bvel2[j * 3 + 0];
            const float vy = bvel2[j * 3 + 1];
            const float vz = bvel2[j * 3 + 2];
            const int row = 3 * r;
#pragma unroll
            for (int c = 0; c < 6; ++c) {
                acc[c] = fmaf(vx, s_Wc[(row + 0) * 6 + c], acc[c]);
                acc[c] = fmaf(vy, s_Wc[(row + 1) * 6 + c], acc[c]);
                acc[c] = fmaf(vz, s_Wc[(row + 2) * 6 + c], acc[c]);
            }
        }
#pragma unroll
        for (int r = 1; r < KNN; ++r) {
            const int j = fi[r];
            const float ox = bpos2[j * 3 + 0] - qx2;
            const float oy = bpos2[j * 3 + 1] - qy2;
            const float oz = bpos2[j * 3 + 2] - qz2;
            const int row = 33 + 3 * (r - 1);
#pragma unroll
            for (int c = 0; c < 6; ++c) {
                acc[c] = fmaf(ox, s_Wc[(row + 0) * 6 + c], acc[c]);
                acc[c] = fmaf(oy, s_Wc[(row + 1) * 6 + c], acc[c]);
                acc[c] = fmaf(oz, s_Wc[(row + 2) * 6 + c], acc[c]);
            }
        }
        {
            const float i0 = initc[bb2 * 3 + 0];
            const float i1 = initc[bb2 * 3 + 1];
            const float i2 = initc[bb2 * 3 + 2];
#pragma unroll
            for (int c = 0; c < 6; ++c) {
                acc[c] = fmaf(i0, s_Wc[63 * 6 + c], acc[c]);
                acc[c] = fmaf(i1, s_Wc[64 * 6 + c], acc[c]);
                acc[c] = fmaf(i2, s_Wc[65 * 6 + c], acc[c]);
            }
        }

        float* o = out + (size_t)qq * 6;
        o[0] = acc[0] + qx2;
        o[1] = acc[1] + qy2;
        o[2] = acc[2] + qz2;
        o[3] = acc[3];
        o[4] = acc[4];
        o[5] = acc[5];
    }
}

// ---------------------------------------------------------------------------
extern "C" void kernel_launch(void* const* d_in, const int* in_sizes, int n_in,
                              void* d_out, int out_size)
{
    const float* position = (const float*)d_in[0];
    const float* velocity = (const float*)d_in[1];
    const float* initcfg  = (const float*)d_in[2];
    const float* W1 = (const float*)d_in[3];
    const float* b1 = (const float*)d_in[4];
    const float* W2 = (const float*)d_in[5];
    const float* b2 = (const float*)d_in[6];
    const float* W3 = (const float*)d_in[7];
    const float* b3 = (const float*)d_in[8];
    float* out = (float*)d_out;

    // Block 0: weight collapse; blocks 1..32: pair packing.
    prologue_kernel<<<1 + (BATCH * PPB + 255) / 256, 256>>>(
        position, W1, b1, W2, b2, W3, b3);

    const int total = BATCH * NPTS;           // 16384 queries
    knn_mlp_kernel<<<total / QPB, TPB>>>(position, velocity, initcfg, out);
}